// round 1
// baseline (speedup 1.0000x reference)
#include <cuda_runtime.h>
#include <cuda_bf16.h>

#define BB   16
#define NN   16384
#define RR   1024
#define DD   320
#define BINS 32
#define HH   512
#define EPSV 1e-5f

// ---------------- scratch (device globals; no allocation allowed) ----------------
__device__ float g_S[BB * RR * BINS];          // segment bin sums   (2 MB)
__device__ int   g_cnt[RR];                    // segment counts
__device__ float g_U[(size_t)BB * RR * HH];    // pooled @ W1[0:32]  (33.5 MB)
__device__ float g_V[(size_t)NN * HH];         // cond @ W1[32:35]+b1 (33.5 MB)
__device__ float g_W2p[3 * HH];                // folded W2, SoA [c][h]
__device__ float g_b2p[3];

// ---------------- kernel 0: zero accumulators ----------------
__global__ void zero_kernel() {
    int idx = blockIdx.x * blockDim.x + threadIdx.x;
    if (idx < BB * RR * BINS) g_S[idx] = 0.0f;
    if (idx < RR) g_cnt[idx] = 0;
}

// ---------------- kernel 1: segment counts ----------------
__global__ void count_kernel(const int* __restrict__ seg) {
    int i = blockIdx.x * blockDim.x + threadIdx.x;
    if (i < NN) atomicAdd(&g_cnt[seg[i]], 1);
}

// ---------------- kernel 2: per-row 10-wide bin sums + segment atomics ----------------
// block = 256 threads, handles 16 rows of x (each row = 320 floats = 80 float4)
__global__ __launch_bounds__(256) void binsum_kernel(const float* __restrict__ x,
                                                     const int* __restrict__ seg) {
    __shared__ float4 smf4[16 * 80];   // 16 rows x 320 floats = 20KB
    float* sm = (float*)smf4;
    int row0 = blockIdx.x * 16;
    const float4* x4 = (const float4*)x;
#pragma unroll
    for (int k = 0; k < 5; k++) {
        int e = k * 256 + threadIdx.x;          // 0..1279
        int rr = e / 80, c4 = e % 80;
        smf4[rr * 80 + c4] = x4[(size_t)(row0 + rr) * 80 + c4];
    }
    __syncthreads();
#pragma unroll
    for (int t = 0; t < 2; t++) {
        int task = t * 256 + threadIdx.x;       // 0..511 = 16 rows x 32 bins
        int rr = task >> 5, bin = task & 31;
        int row = row0 + rr;
        int b = row >> 14;                      // row / NN
        int i = row & (NN - 1);
        float s = 0.0f;
#pragma unroll
        for (int j = 0; j < 10; j++) s += sm[rr * 320 + bin * 10 + j];
        atomicAdd(&g_S[((b << 10) + seg[i]) * BINS + bin], s);
    }
}

// ---------------- kernel 3: U[b,r,:] = pooled[b,r,:] @ W1[0:32,:] ----------------
// grid = B*R blocks, 128 threads
__global__ __launch_bounds__(128) void u_kernel(const float* __restrict__ W1) {
    int br = blockIdx.x;                 // b*R + r
    int r = br & (RR - 1);
    __shared__ float pooled[BINS];
    if (threadIdx.x < BINS) {
        float c = (float)max(g_cnt[r], 1);
        pooled[threadIdx.x] = g_S[br * BINS + threadIdx.x] / (10.0f * c);
    }
    __syncthreads();
#pragma unroll
    for (int q = 0; q < 4; q++) {
        int h = q * 128 + threadIdx.x;
        float acc = 0.0f;
#pragma unroll
        for (int bin = 0; bin < BINS; bin++) acc += pooled[bin] * W1[bin * HH + h];
        g_U[(size_t)br * HH + h] = acc;
    }
}

// ---------------- kernel 4: V[i,:] = cond[i,:] @ W1[32:35,:] + b1 ----------------
__global__ __launch_bounds__(256) void v_kernel(const float* __restrict__ cond,
                                                const float* __restrict__ W1,
                                                const float* __restrict__ b1) {
    int idx = blockIdx.x * blockDim.x + threadIdx.x;   // over N * 128 float4
    int i = idx >> 7, h4 = idx & 127;
    float c0 = cond[i * 3 + 0], c1 = cond[i * 3 + 1], c2 = cond[i * 3 + 2];
    const float4* W1r = (const float4*)(W1 + 32 * HH);
    float4 w0 = W1r[h4], w1 = W1r[128 + h4], w2 = W1r[256 + h4];
    float4 bb = ((const float4*)b1)[h4];
    float4 v;
    v.x = c0 * w0.x + c1 * w1.x + c2 * w2.x + bb.x;
    v.y = c0 * w0.y + c1 * w1.y + c2 * w2.y + bb.y;
    v.z = c0 * w0.z + c1 * w1.z + c2 * w2.z + bb.z;
    v.w = c0 * w0.w + c1 * w1.w + c2 * w2.w + bb.w;
    ((float4*)g_V)[idx] = v;
}

// ---------------- kernel 5: fold batchnorm into W2 ----------------
__global__ void w2p_kernel(const float* __restrict__ gamma, const float* __restrict__ beta,
                           const float* __restrict__ bn_mean, const float* __restrict__ bn_var,
                           const float* __restrict__ W2, const float* __restrict__ b2) {
    __shared__ float red[HH];
    int h = threadIdx.x;
    float s = rsqrtf(bn_var[h] + EPSV) * gamma[h];
    float t = beta[h] - bn_mean[h] * s;
    for (int c = 0; c < 3; c++) {
        g_W2p[c * HH + h] = W2[h * 3 + c] * s;
        red[h] = t * W2[h * 3 + c];
        __syncthreads();
        for (int off = 256; off; off >>= 1) {
            if (h < off) red[h] += red[h + off];
            __syncthreads();
        }
        if (h == 0) g_b2p[c] = b2[c] + red[0];
        __syncthreads();
    }
}

// ---------------- kernel 6: out[b,i,:] = relu(U[b,seg_i,:]+V[i,:]) @ W2p + b2p ----------------
// warp per atom i, loop over all 16 b; lane handles 16 h (4 float4)
__global__ __launch_bounds__(256) void main_kernel(const int* __restrict__ seg,
                                                   float* __restrict__ out) {
    int warp = threadIdx.x >> 5, lane = threadIdx.x & 31;
    int i = blockIdx.x * 8 + warp;
    int s = seg[i];

    const float4* V4 = (const float4*)g_V + (size_t)i * 128;
    const float4* W2p4 = (const float4*)g_W2p;
    float4 vr[4], p0[4], p1[4], p2[4];
#pragma unroll
    for (int q = 0; q < 4; q++) {
        int h4 = q * 32 + lane;
        vr[q] = V4[h4];
        p0[q] = W2p4[h4];
        p1[q] = W2p4[128 + h4];
        p2[q] = W2p4[256 + h4];
    }
    float bp0 = g_b2p[0], bp1 = g_b2p[1], bp2 = g_b2p[2];

#pragma unroll 1
    for (int b = 0; b < BB; b++) {
        const float4* U4 = (const float4*)g_U + (size_t)(b * RR + s) * 128;
        float a0 = 0.0f, a1 = 0.0f, a2 = 0.0f;
#pragma unroll
        for (int q = 0; q < 4; q++) {
            float4 u = U4[q * 32 + lane];
            float z;
            z = fmaxf(u.x + vr[q].x, 0.0f); a0 += z * p0[q].x; a1 += z * p1[q].x; a2 += z * p2[q].x;
            z = fmaxf(u.y + vr[q].y, 0.0f); a0 += z * p0[q].y; a1 += z * p1[q].y; a2 += z * p2[q].y;
            z = fmaxf(u.z + vr[q].z, 0.0f); a0 += z * p0[q].z; a1 += z * p1[q].z; a2 += z * p2[q].z;
            z = fmaxf(u.w + vr[q].w, 0.0f); a0 += z * p0[q].w; a1 += z * p1[q].w; a2 += z * p2[q].w;
        }
#pragma unroll
        for (int off = 16; off; off >>= 1) {
            a0 += __shfl_xor_sync(0xffffffffu, a0, off);
            a1 += __shfl_xor_sync(0xffffffffu, a1, off);
            a2 += __shfl_xor_sync(0xffffffffu, a2, off);
        }
        if (lane == 0) {
            size_t o = ((size_t)b * NN + i) * 3;
            out[o + 0] = a0 + bp0;
            out[o + 1] = a1 + bp1;
            out[o + 2] = a2 + bp2;
        }
    }
}

// ---------------- launch ----------------
extern "C" void kernel_launch(void* const* d_in, const int* in_sizes, int n_in,
                              void* d_out, int out_size) {
    const float* x       = (const float*)d_in[0];
    const float* cond    = (const float*)d_in[1];
    const int*   seg     = (const int*)  d_in[2];
    const float* W1      = (const float*)d_in[3];
    const float* b1      = (const float*)d_in[4];
    const float* gamma   = (const float*)d_in[5];
    const float* beta    = (const float*)d_in[6];
    const float* bn_mean = (const float*)d_in[7];
    const float* bn_var  = (const float*)d_in[8];
    const float* W2      = (const float*)d_in[9];
    const float* b2      = (const float*)d_in[10];
    float* out = (float*)d_out;

    zero_kernel<<<(BB * RR * BINS + 255) / 256, 256>>>();
    count_kernel<<<NN / 256, 256>>>(seg);
    binsum_kernel<<<(BB * NN) / 16, 256>>>(x, seg);
    u_kernel<<<BB * RR, 128>>>(W1);
    v_kernel<<<(NN * (HH / 4)) / 256, 256>>>(cond, W1, b1);
    w2p_kernel<<<1, HH>>>(gamma, beta, bn_mean, bn_var, W2, b2);
    main_kernel<<<NN / 8, 256>>>(seg, out);
}